// round 16
// baseline (speedup 1.0000x reference)
#include <cuda_runtime.h>

// VQ_86139864089353: per-dimension 1D vector quantization — 3 kernels.
// ze: (B, D, 1) f32 ; e: (K, D) f32.  out: [ z (B*D) f32 | zq (B*D) f32 ]
//
// R6/R14-validated math. vq_main reads the 24 KB of tables directly from
// global via __ldg (L1-resident per SM) — no per-block smem broadcast, no
// preamble barrier, no smem at all.

#define BN      262144
#define DDIM    3
#define KK      512
#define NBD     (BN * DDIM)
#define NEL     (BN * DDIM)
#define NCELL   2048
#define FLO     (-4.0f)
#define FW      (8.0f / (float)NCELL)    // 1/256 (dyadic)
#define FINVW   ((float)NCELL / 8.0f)    // 256   (dyadic)
#define JPARTS  16
#define JCH     (KK / JPARTS)            // 32

#define MBLK    512
#define MVEC    2
#define MGRID   (NEL / (MBLK * MVEC))    // 768

__device__ int            g_rankp[DDIM][JPARTS][KK];
__device__ float2         g_pair[DDIM][KK];    // {sorted value, (float)orig}
__device__ unsigned short g_lut[DDIM][NCELL];

// Monotone (order-preserving) uint32 map of an IEEE754 float.
__device__ __forceinline__ unsigned fkey(float f) {
    unsigned u = __float_as_uint(f);
    return u ^ ((unsigned)((int)u >> 31) | 0x80000000u);
}

// ---------------------------------------------------------------------------
// Kernel 1: partial stable ranks via 64-bit keys. grid (DDIM, JPARTS) x 512.
// key = mono(value):index  ->  (kj < kk) == (vj<vk || (vj==vk && j<k))
// ---------------------------------------------------------------------------
__global__ void vq_rank(const float* __restrict__ e) {
    const int d = blockIdx.x;
    const int p = blockIdx.y;
    const int k = threadIdx.x;

    __shared__ unsigned long long s_k[JCH];
    if (k < JCH) {
        int j = p * JCH + k;
        s_k[k] = ((unsigned long long)fkey(e[j * DDIM + d]) << 16) | (unsigned)j;
    }
    __syncthreads();

    const unsigned long long kv =
        ((unsigned long long)fkey(e[k * DDIM + d]) << 16) | (unsigned)k;
    int r = 0;
#pragma unroll
    for (int j = 0; j < JCH; ++j)
        r += (s_k[j] < kv);
    g_rankp[d][p][k] = r;
}

// ---------------------------------------------------------------------------
// Kernel 2: combine partials, scatter to sorted order, LUT. grid DDIM x KK.
// ---------------------------------------------------------------------------
__global__ void vq_build(const float* __restrict__ e) {
    const int d = blockIdx.x;
    const int k = threadIdx.x;   // 0..511

    int r = 0;
#pragma unroll
    for (int p = 0; p < JPARTS; ++p)
        r += g_rankp[d][p][k];

    __shared__ float s_sorted[KK];
    __shared__ short s_org[KK];
    s_sorted[r] = e[k * DDIM + d];
    s_org[r]    = (short)k;
    __syncthreads();

    g_pair[d][k] = make_float2(s_sorted[k], (float)s_org[k]);

    // LUT: conservative lower bound on insertion position, one-cell guard.
    for (int c = k; c < NCELL; c += KK) {
        float edge = FLO + (float)c * FW - FW;
        int lo = 0, hi = KK;
        while (lo < hi) {
            int m = (lo + hi) >> 1;
            if (s_sorted[m] < edge) lo = m + 1; else hi = m;
        }
        g_lut[d][c] = (unsigned short)lo;
    }
}

// ---------------------------------------------------------------------------
// Kernel 3: main. 2 elements/thread; tables read via __ldg (L1-resident).
// ---------------------------------------------------------------------------
__global__ void __launch_bounds__(MBLK, 4)
vq_main(const float2* __restrict__ ze2, float* __restrict__ out) {
    const int tid = threadIdx.x;
    const int t   = blockIdx.x * MBLK + tid;     // float2 index
    const int n0  = t * MVEC;

    float2 xv = ze2[t];
    float xs[MVEC] = {xv.x, xv.y};
    float rz[MVEC], rq[MVEC];

    int d = n0 % 3;
#pragma unroll
    for (int j = 0; j < MVEC; ++j) {
        const float x = xs[j];
        const float2* __restrict__ tab = &g_pair[d][0];

        float tt = fminf(fmaxf((x - FLO) * FINVW, 0.0f), (float)(NCELL - 1));
        int i = __ldg(&g_lut[d][(int)tt]);
        while (i < KK && __ldg(&tab[i].x) <= x) ++i;

        // Clamp once: [i2-2, i2+1] always in range, superset of the true
        // candidate pair {i-1, i} plus same-side tie neighbors.
        int i2 = i < 2 ? 2 : (i > KK - 2 ? KK - 2 : i);

        // exact fp32 argmin, tie -> min original index (reference semantics)
        float bestD = __int_as_float(0x7f800000);
        float bestO = 1.0e9f;
        float bestV = 0.0f;
#pragma unroll
        for (int off = -2; off <= 1; ++off) {
            float2 p = __ldg(&tab[i2 + off]);
            float dx = x - p.x;
            float dd = dx * dx;                  // same fp32 op as reference
            bool take = (dd < bestD) || (dd == bestD && p.y < bestO);
            bestD = take ? dd : bestD;
            bestO = take ? p.y : bestO;
            bestV = take ? p.x : bestV;
        }
        rz[j] = bestO;
        rq[j] = bestV;

        d = (d == 2) ? 0 : d + 1;
    }

    ((float2*)out)[t]         = make_float2(rz[0], rz[1]);
    ((float2*)(out + NBD))[t] = make_float2(rq[0], rq[1]);
}

// ---------------------------------------------------------------------------
extern "C" void kernel_launch(void* const* d_in, const int* in_sizes, int n_in,
                              void* d_out, int out_size) {
    const float* ze = (const float*)d_in[0];   // (B, D, 1)
    const float* e  = (const float*)d_in[1];   // (K, D)
    float* out = (float*)d_out;

    vq_rank<<<dim3(DDIM, JPARTS), KK>>>(e);
    vq_build<<<DDIM, KK>>>(e);
    vq_main<<<MGRID, MBLK>>>((const float2*)ze, out);
}

// round 17
// speedup vs baseline: 1.2553x; 1.2553x over previous
#include <cuda_runtime.h>

// VQ_86139864089353: per-dimension 1D vector quantization — 3 kernels.
// ze: (B, D, 1) f32 ; e: (K, D) f32.  out: [ z (B*D) f32 | zq (B*D) f32 ]
//
// R14-validated math. vq_main is now a single-wave persistent grid
// (296 CTAs = 2/SM): blocks 0..87 handle two tiles, preamble count drops
// 384 -> 296, no wave-2 tail, tile-2 input loads overlap the broadcast.

#define BN      262144
#define DDIM    3
#define KK      512
#define NBD     (BN * DDIM)
#define NEL     (BN * DDIM)
#define NCELL   2048
#define FLO     (-4.0f)
#define FW      (8.0f / (float)NCELL)    // 1/256 (dyadic)
#define FINVW   ((float)NCELL / 8.0f)    // 256   (dyadic)
#define JPARTS  16
#define JCH     (KK / JPARTS)            // 32

#define MBLK    1024
#define MVEC    2
#define NF2     (NEL / MVEC)             // 393216 float2 total
#define MGRID   296                      // 2 CTAs x 148 SMs, single wave
#define TILE2   (MGRID * MBLK)           // 303104; tail = 88 * MBLK

__device__ int            g_rankp[DDIM][JPARTS][KK];
__device__ float2         g_pair[DDIM][KK];    // {sorted value, (float)orig}
__device__ unsigned short g_lut[DDIM][NCELL];

// Monotone (order-preserving) uint32 map of an IEEE754 float.
__device__ __forceinline__ unsigned fkey(float f) {
    unsigned u = __float_as_uint(f);
    return u ^ ((unsigned)((int)u >> 31) | 0x80000000u);
}

// ---------------------------------------------------------------------------
// Kernel 1: partial stable ranks via 64-bit keys. grid (DDIM, JPARTS) x 512.
// key = mono(value):index  ->  (kj < kk) == (vj<vk || (vj==vk && j<k))
// ---------------------------------------------------------------------------
__global__ void vq_rank(const float* __restrict__ e) {
    const int d = blockIdx.x;
    const int p = blockIdx.y;
    const int k = threadIdx.x;

    __shared__ unsigned long long s_k[JCH];
    if (k < JCH) {
        int j = p * JCH + k;
        s_k[k] = ((unsigned long long)fkey(e[j * DDIM + d]) << 16) | (unsigned)j;
    }
    __syncthreads();

    const unsigned long long kv =
        ((unsigned long long)fkey(e[k * DDIM + d]) << 16) | (unsigned)k;
    int r = 0;
#pragma unroll
    for (int j = 0; j < JCH; ++j)
        r += (s_k[j] < kv);
    g_rankp[d][p][k] = r;
}

// ---------------------------------------------------------------------------
// Kernel 2: combine partials, scatter to sorted order, LUT. grid DDIM x KK.
// ---------------------------------------------------------------------------
__global__ void vq_build(const float* __restrict__ e) {
    const int d = blockIdx.x;
    const int k = threadIdx.x;   // 0..511

    int r = 0;
#pragma unroll
    for (int p = 0; p < JPARTS; ++p)
        r += g_rankp[d][p][k];

    __shared__ float s_sorted[KK];
    __shared__ short s_org[KK];
    s_sorted[r] = e[k * DDIM + d];
    s_org[r]    = (short)k;
    __syncthreads();

    g_pair[d][k] = make_float2(s_sorted[k], (float)s_org[k]);

    // LUT: conservative lower bound on insertion position, one-cell guard.
    for (int c = k; c < NCELL; c += KK) {
        float edge = FLO + (float)c * FW - FW;
        int lo = 0, hi = KK;
        while (lo < hi) {
            int m = (lo + hi) >> 1;
            if (s_sorted[m] < edge) lo = m + 1; else hi = m;
        }
        g_lut[d][c] = (unsigned short)lo;
    }
}

// ---------------------------------------------------------------------------
// Quantize one float2 (elements n0 = t*2 and t*2+1) using smem tables.
// ---------------------------------------------------------------------------
__device__ __forceinline__ void vq_pair(
    const float2 xv, const int t,
    const float2 (*s_pair)[KK], const unsigned short (*s_lut)[NCELL],
    float* __restrict__ out)
{
    const int n0 = t * MVEC;
    float xs[MVEC] = {xv.x, xv.y};
    float rz[MVEC], rq[MVEC];

    int d = n0 % 3;
#pragma unroll
    for (int j = 0; j < MVEC; ++j) {
        const float x = xs[j];

        float tt = fminf(fmaxf((x - FLO) * FINVW, 0.0f), (float)(NCELL - 1));
        int i = s_lut[d][(int)tt];
        while (i < KK && s_pair[d][i].x <= x) ++i;

        // Clamp once: [i2-2, i2+1] always in range, superset of the true
        // candidate pair {i-1, i} plus same-side tie neighbors.
        int i2 = i < 2 ? 2 : (i > KK - 2 ? KK - 2 : i);

        // exact fp32 argmin, tie -> min original index (reference semantics)
        float bestD = __int_as_float(0x7f800000);
        float bestO = 1.0e9f;
        float bestV = 0.0f;
#pragma unroll
        for (int off = -2; off <= 1; ++off) {
            float2 p = s_pair[d][i2 + off];
            float dx = x - p.x;
            float dd = dx * dx;                  // same fp32 op as reference
            bool take = (dd < bestD) || (dd == bestD && p.y < bestO);
            bestD = take ? dd : bestD;
            bestO = take ? p.y : bestO;
            bestV = take ? p.x : bestV;
        }
        rz[j] = bestO;
        rq[j] = bestV;

        d = (d == 2) ? 0 : d + 1;
    }

    ((float2*)out)[t]         = make_float2(rz[0], rz[1]);
    ((float2*)(out + NBD))[t] = make_float2(rq[0], rq[1]);
}

// ---------------------------------------------------------------------------
// Kernel 3: main. Persistent single wave: 296 CTAs x 1024 threads.
// Blocks 0..87 handle tiles {t, t+TILE2}; blocks 88..295 handle {t}.
// ---------------------------------------------------------------------------
__global__ void __launch_bounds__(MBLK, 2)
vq_main(const float2* __restrict__ ze2, float* __restrict__ out) {
    __shared__ float2         s_pair[DDIM][KK];      // 12 KB
    __shared__ unsigned short s_lut[DDIM][NCELL];    // 12 KB

    const int tid = threadIdx.x;
    const int t0  = blockIdx.x * MBLK + tid;
    const int t1  = t0 + TILE2;
    const bool two = (t1 < NF2);                     // uniform per block

    // Prefetch inputs BEFORE the table broadcast (hides DRAM latency).
    float2 xv0 = ze2[t0];
    float2 xv1 = two ? ze2[t1] : make_float2(0.f, 0.f);

    // Table broadcast (global -> smem), vectorized.
    {
        const float4* src = (const float4*)g_pair;
        float4*       dst = (float4*)s_pair;
        for (int i = tid; i < (int)(DDIM * KK * sizeof(float2) / 16); i += MBLK)
            dst[i] = src[i];
    }
    {
        const uint4* src = (const uint4*)g_lut;
        uint4*       dst = (uint4*)s_lut;
        for (int i = tid; i < (int)(DDIM * NCELL * sizeof(short) / 16); i += MBLK)
            dst[i] = src[i];
    }
    __syncthreads();

    vq_pair(xv0, t0, s_pair, s_lut, out);
    if (two)
        vq_pair(xv1, t1, s_pair, s_lut, out);
}

// ---------------------------------------------------------------------------
extern "C" void kernel_launch(void* const* d_in, const int* in_sizes, int n_in,
                              void* d_out, int out_size) {
    const float* ze = (const float*)d_in[0];   // (B, D, 1)
    const float* e  = (const float*)d_in[1];   // (K, D)
    float* out = (float*)d_out;

    vq_rank<<<dim3(DDIM, JPARTS), KK>>>(e);
    vq_build<<<DDIM, KK>>>(e);
    vq_main<<<MGRID, MBLK>>>((const float2*)ze, out);
}